// round 1
// baseline (speedup 1.0000x reference)
#include <cuda_runtime.h>

// Problem constants (hardcoded from reference setup_inputs):
//   poses:       (4, 16, 16, 32, 4, 4)  float32
//   activations: (4, 16, 16, 32, 1, 1)  float32
//   pose_kernel: (3, 3, 32, 32, 4, 4)   float32
//   votes out:   (4, 14, 14, 3, 3, 32, 32, 4, 4)
//   act out:     (4, 14, 14, 3, 3, 32, 1, 1, 1)
// einsum has no contraction -> votes is an elementwise broadcast product.

constexpr int B  = 4;
constexpr int H  = 16;
constexpr int W  = 16;
constexpr int OH = 14;
constexpr int OW = 14;
constexpr int KS = 3;
constexpr int IC = 32;
constexpr int OC = 32;
constexpr int AT = 16;  // 4x4 pose atom

// number of (b,h,w,ky,kx,i) tuples
constexpr int NPOS = B * OH * OW * KS * KS * IC;            // 225792
constexpr long long VOTES_ELEMS = (long long)NPOS * OC * AT; // 115,605,504

// One warp per (b,h,w,ky,kx,i); lane = out-capsule o.
// Lane reads the (uniform) 16-float pose atom + its own 16-float kernel atom,
// multiplies, and streams 16 floats out. Warp-level: 2KB contiguous kernel
// read, 2KB contiguous store. Fully coalesced 128-bit accesses.
__global__ __launch_bounds__(256) void votes_kernel(
    const float* __restrict__ poses,
    const float* __restrict__ pk,
    float* __restrict__ out)
{
    int gwarp = (blockIdx.x * blockDim.x + threadIdx.x) >> 5;
    int lane  = threadIdx.x & 31;
    if (gwarp >= NPOS) return;

    int t = gwarp;
    int i = t & 31;  t >>= 5;     // in-capsule
    int y = t % KS;  t /= KS;     // kx
    int x = t % KS;  t /= KS;     // ky
    int w = t % OW;  t /= OW;
    int h = t % OH;  t /= OH;
    int b = t;

    // pose atom for (b, h+x, w+y, i): 16 contiguous floats (64B aligned)
    const float4* pv = reinterpret_cast<const float4*>(
        poses + (((((long long)b * H + (h + x)) * W + (w + y)) * IC + i) * AT));
    // kernel atom for (x, y, i, lane): 16 contiguous floats per lane
    const float4* kv = reinterpret_cast<const float4*>(
        pk + ((((long long)(x * KS + y) * IC + i) * OC + lane) * AT));
    // output atom for (gwarp, lane)
    float4* ov = reinterpret_cast<float4*>(
        out + (((long long)gwarp * OC + lane) * AT));

#pragma unroll
    for (int j = 0; j < 4; ++j) {
        float4 p = pv[j];
        float4 k = kv[j];
        float4 o;
        o.x = p.x * k.x;
        o.y = p.y * k.y;
        o.z = p.z * k.z;
        o.w = p.w * k.w;
        ov[j] = o;
    }
}

// act_out[b,h,w,x,y,i] = activations[b, h+x, w+y, i]
__global__ __launch_bounds__(256) void act_kernel(
    const float* __restrict__ act,
    float* __restrict__ out)
{
    int idx = blockIdx.x * blockDim.x + threadIdx.x;
    if (idx >= NPOS) return;

    int t = idx;
    int i = t & 31;  t >>= 5;
    int y = t % KS;  t /= KS;
    int x = t % KS;  t /= KS;
    int w = t % OW;  t /= OW;
    int h = t % OH;  t /= OH;
    int b = t;

    out[idx] = act[(((b * H + (h + x)) * W + (w + y)) * IC) + i];
}

extern "C" void kernel_launch(void* const* d_in, const int* in_sizes, int n_in,
                              void* d_out, int out_size)
{
    const float* poses = (const float*)d_in[0];
    const float* acts  = (const float*)d_in[1];
    const float* pk    = (const float*)d_in[2];
    float* out = (float*)d_out;

    // votes: NPOS warps, 256 threads/block -> 8 warps/block
    {
        int total_threads = NPOS * 32;
        int threads = 256;
        int blocks = (total_threads + threads - 1) / threads;
        votes_kernel<<<blocks, threads>>>(poses, pk, out);
    }
    // act_out appended after votes
    {
        int threads = 256;
        int blocks = (NPOS + threads - 1) / threads;
        act_kernel<<<blocks, threads>>>(acts, out + VOTES_ELEMS);
    }
}

// round 2
// speedup vs baseline: 2.1761x; 2.1761x over previous
#include <cuda_runtime.h>

// Problem constants (from reference setup_inputs):
//   poses:       (4, 16, 16, 32, 4, 4)  float32
//   activations: (4, 16, 16, 32, 1, 1)  float32
//   pose_kernel: (3, 3, 32, 32, 4, 4)   float32
//   votes out:   (4, 14, 14, 3, 3, 32, 32, 4, 4)
//   act out:     (4, 14, 14, 3, 3, 32, 1, 1, 1)   appended after votes
// einsum has no contraction -> votes is an elementwise broadcast product:
//   votes[b,h,w,x,y,i,o,m,n] = poses[b,h+x,w+y,i,m,n] * pk[x,y,i,o,m,n]

constexpr int B  = 4;
constexpr int H  = 16;
constexpr int W  = 16;
constexpr int OH = 14;
constexpr int OW = 14;
constexpr int KS = 3;
constexpr int IC = 32;
constexpr int OC = 32;
constexpr int AT = 16;  // 4x4 pose atom

constexpr int NPOS = B * OH * OW * KS * KS * IC;             // 225792 tuples
constexpr long long VOTES_ELEMS = (long long)NPOS * OC * AT; // 115,605,504

// One warp per (b,h,w,ky,kx,i) tuple. The tuple's output block is 512
// contiguous floats ([o][m][n]); the matching pose_kernel block is also 512
// contiguous floats. Flatten both: lane l, iter j handles float4 #(j*32+l)
// of the 128-float4 block -> every LDG/STG.128 is a fully contiguous 512B
// warp transaction (minimal L1tex wavefronts). The pose operand for float4
// #f4 is pose-atom float4 #(f4 & 3) -> 4-way broadcast load, L1-resident.
// Lane 0 additionally writes the single act_out element for this tuple
// (fuses the second kernel away).
__global__ __launch_bounds__(256) void fused_kernel(
    const float* __restrict__ poses,
    const float* __restrict__ act,
    const float* __restrict__ pk,
    float* __restrict__ votes_out,
    float* __restrict__ act_out)
{
    int gwarp = (blockIdx.x * blockDim.x + threadIdx.x) >> 5;
    int lane  = threadIdx.x & 31;
    if (gwarp >= NPOS) return;

    int t = gwarp;
    int i = t & 31;  t >>= 5;     // in-capsule
    int y = t % KS;  t /= KS;     // kx
    int x = t % KS;  t /= KS;     // ky
    int w = t % OW;  t /= OW;
    int h = t % OH;  t /= OH;
    int b = t;

    int src_pix = ((b * H + (h + x)) * W + (w + y)) * IC + i;

    // pose atom: 4 float4s; this lane always uses atom float4 #(lane & 3)
    const float4* pv = reinterpret_cast<const float4*>(poses) + src_pix * 4 + (lane & 3);
    float4 p = *pv;

    // kernel block for (x,y,i): 128 contiguous float4s
    const float4* kv = reinterpret_cast<const float4*>(pk)
                     + (long long)((x * KS + y) * IC + i) * (OC * AT / 4);
    // output block: 128 contiguous float4s
    float4* ov = reinterpret_cast<float4*>(votes_out)
               + (long long)gwarp * (OC * AT / 4);

#pragma unroll
    for (int j = 0; j < 4; ++j) {
        float4 k = kv[j * 32 + lane];
        float4 o;
        o.x = p.x * k.x;
        o.y = p.y * k.y;
        o.z = p.z * k.z;
        o.w = p.w * k.w;
        ov[j * 32 + lane] = o;
    }

    if (lane == 0) {
        act_out[gwarp] = act[src_pix];
    }
}

extern "C" void kernel_launch(void* const* d_in, const int* in_sizes, int n_in,
                              void* d_out, int out_size)
{
    const float* poses = (const float*)d_in[0];
    const float* acts  = (const float*)d_in[1];
    const float* pk    = (const float*)d_in[2];
    float* out = (float*)d_out;

    int total_threads = NPOS * 32;
    int threads = 256;
    int blocks = (total_threads + threads - 1) / threads;
    fused_kernel<<<blocks, threads>>>(poses, acts, pk, out, out + VOTES_ELEMS);
}